// round 14
// baseline (speedup 1.0000x reference)
#include <cuda_runtime.h>
#include <cuda_fp16.h>
#include <cstdint>

// Problem constants (fixed by the reference)
#define B_  8
#define S_  2048
#define D_  512
#define H_  8
#define DH_ 64
#define M_  (B_ * S_)          // 16384 rows for all projections

// Scratch (allocation-free rule: __device__ globals)
// Compact per-plane fp16 streams, row-major [rows, 512]
__device__ unsigned short g_xQh[M_ * D_];
__device__ unsigned short g_xKh[M_ * D_];
__device__ unsigned short g_xVh[M_ * D_];
__device__ unsigned short g_Wqh[D_ * D_];
__device__ unsigned short g_Wkh[D_ * D_];
__device__ unsigned short g_Wvh[D_ * D_];
__device__ unsigned short g_Wvl[D_ * D_];
__device__ unsigned short g_Woh[D_ * D_];
__device__ unsigned short g_Wol[D_ * D_];
__device__ unsigned short g_ctxh[M_ * D_];
__device__ unsigned short g_ctxl[M_ * D_];
// Attention operands, pure fp16:
__device__ unsigned short g_Qf[B_ * H_ * S_ * DH_];      // [b,h,s,d] fp16
__device__ unsigned short g_Kf[B_ * H_ * S_ * DH_];      // [b,h,s,d] fp16
__device__ unsigned short g_Vf[B_ * H_ * DH_ * S_];      // [b,h,d,s] fp16

__device__ __forceinline__ float ex2f(float x) {
    float y;
    asm("ex2.approx.f32 %0, %1;" : "=f"(y) : "f"(x));
    return y;
}

__device__ __forceinline__ uint32_t smem_u32(const void* p) {
    uint32_t a;
    asm("{ .reg .u64 t; cvta.to.shared.u64 t, %1; cvt.u32.u64 %0, t; }" : "=r"(a) : "l"(p));
    return a;
}

__device__ __forceinline__ void cp16(uint32_t dst, const void* src) {
    asm volatile("cp.async.cg.shared.global [%0], [%1], 16;" :: "r"(dst), "l"(src) : "memory");
}
#define CP_COMMIT() asm volatile("cp.async.commit_group;" ::: "memory")
template <int N>
__device__ __forceinline__ void cp_wait() {
    asm volatile("cp.async.wait_group %0;" :: "n"(N) : "memory");
}

__device__ __forceinline__ void ldmatrix4(uint32_t* r, uint32_t addr) {
    asm volatile("ldmatrix.sync.aligned.m8n8.x4.shared.b16 {%0,%1,%2,%3}, [%4];"
                 : "=r"(r[0]), "=r"(r[1]), "=r"(r[2]), "=r"(r[3]) : "r"(addr));
}

__device__ __forceinline__ void mma_f16(float* d, const uint32_t* a,
                                        uint32_t b0, uint32_t b1) {
    asm volatile(
        "mma.sync.aligned.m16n8k16.row.col.f32.f16.f16.f32 "
        "{%0,%1,%2,%3}, {%4,%5,%6,%7}, {%8,%9}, {%0,%1,%2,%3};"
        : "+f"(d[0]), "+f"(d[1]), "+f"(d[2]), "+f"(d[3])
        : "r"(a[0]), "r"(a[1]), "r"(a[2]), "r"(a[3]), "r"(b0), "r"(b1));
}

// fp32 -> fp16 hi/lo bits (scalar)
__device__ __forceinline__ void hsplit(float f, unsigned short& hi, unsigned short& lo) {
    __half h = __float2half_rn(f);
    float hf = __half2float(h);
    __half l = __float2half_rn(f - hf);
    hi = __half_as_ushort(h);
    lo = __half_as_ushort(l);
}

// two fp32 -> packed fp16x2 hi pair + lo pair
__device__ __forceinline__ void hsplit2(float x, float y, uint32_t& hi2, uint32_t& lo2) {
    __half2 h = __floats2half2_rn(x, y);
    float2 hf = __half22float2(h);
    __half2 l = __floats2half2_rn(x - hf.x, y - hf.y);
    hi2 = *reinterpret_cast<uint32_t*>(&h);
    lo2 = *reinterpret_cast<uint32_t*>(&l);
}

// ============================================================================
// Pack pass: fp32 row-major -> compact fp16 hi stream (+ optional lo stream)
// ============================================================================
struct PackArgs {
    const float*    src[4];
    unsigned short* dh[4];
    unsigned short* dl[4];     // null -> skip lo
    int n;
};

__global__ __launch_bounds__(256) void pack_h16(PackArgs pa)
{
    const float* src = pa.src[blockIdx.y];
    unsigned short* dh = pa.dh[blockIdx.y];
    unsigned short* dl = pa.dl[blockIdx.y];
    int e = (blockIdx.x * 256 + threadIdx.x) * 8;
    if (e >= pa.n) return;

    float4 v0 = *(const float4*)(src + e);
    float4 v1 = *(const float4*)(src + e + 4);
    unsigned short hb[8], lb[8];
    hsplit(v0.x, hb[0], lb[0]); hsplit(v0.y, hb[1], lb[1]);
    hsplit(v0.z, hb[2], lb[2]); hsplit(v0.w, hb[3], lb[3]);
    hsplit(v1.x, hb[4], lb[4]); hsplit(v1.y, hb[5], lb[5]);
    hsplit(v1.z, hb[6], lb[6]); hsplit(v1.w, hb[7], lb[7]);
    *(uint4*)(dh + e) = *(uint4*)hb;
    if (dl) *(uint4*)(dl + e) = *(uint4*)lb;
}

// ============================================================================
// Split-fp16 projection GEMM, compact per-plane streams, cp.async 2-stage.
//   C = A @ W^T;  nterm: 1 = Ah*Wh;  2 = +Ah*Wl;  3 = +Al*Wh (exact).
//   CTA: 64m x 128n, 256 threads (8 warps, 32x32 warp tiles), chunk = 64 k.
//   Tile shape preserves A-side traffic (4 n-tile columns); W re-reads hit L2.
//   Stage layout: [Ah 8KB][Wh 16KB][Wl 16KB][Al 8KB(3-term only)].
//   2 stages + launch_bounds(256,2) -> 2 CTAs/SM (regs+smem both fit).
//   mode 0: fp16 [b,h,s,d] (Q/K)   mode 2: fp32 [M,512]   mode 3: fp16 [b,h,d,s] (V)
// ============================================================================
struct ProjArgs {
    const unsigned short* Ah[3];
    const unsigned short* Al[3];
    const unsigned short* Wh[3];
    const unsigned short* Wl[3];
    const float* bias[3];
    void* out[3];
    float scale[3];
    int mode[3];
    int nterm[3];
};

#define PJ_SMEM_MAX 98304   // 2 x 48KB (final proj)

__global__ __launch_bounds__(256, 2) void proj_mma(ProjArgs pa, int stage_b)
{
    const int z = blockIdx.z;
    const unsigned short* Ahp = pa.Ah[z];
    const unsigned short* Alp = pa.Al[z];
    const unsigned short* Whp = pa.Wh[z];
    const unsigned short* Wlp = pa.Wl[z];
    const float* bias = pa.bias[z];
    void* outv = pa.out[z];
    const float scale = pa.scale[z];
    const int mode = pa.mode[z];
    const int nterm = pa.nterm[z];

    extern __shared__ __align__(16) char smem[];
    const uint32_t sbase = smem_u32(smem);

    const int tid = threadIdx.x;
    const int lane = tid & 31;
    const int warp = tid >> 5;         // 0..7
    const int wm = warp >> 2;          // 0..1
    const int wn = warp & 3;           // 0..3
    const int m0 = blockIdx.y * 64;
    const int n0 = blockIdx.x * 128;

    // loaders: A = 64 rows x 128B (2 cp16/thread), W = 128 rows x 128B (4 cp16/thread)
    const int arow = tid >> 2;         // 0..63
    const int as0  = (tid & 3) * 2;    // 2 segs
    const int wrow = tid >> 1;         // 0..127
    const int ws0  = (tid & 1) * 4;    // 4 segs

    auto loadc = [&](int c, int st) {
        const uint32_t base = sbase + st * stage_b;
        {
            const size_t g = (size_t)(m0 + arow) * 512 + c * 64;
            const int rx = arow & 7;
            const uint32_t rb = base + arow * 128;
#pragma unroll
            for (int j = 0; j < 2; ++j) {
                int seg = as0 + j;
                uint32_t off = 16u * (uint32_t)(seg ^ rx);
                cp16(rb + off, Ahp + g + seg * 8);
                if (nterm >= 3) cp16(rb + 40960 + off, Alp + g + seg * 8);
            }
        }
        {
            const size_t g = (size_t)(n0 + wrow) * 512 + c * 64;
            const int rx = wrow & 7;
            const uint32_t rb = base + 8192 + wrow * 128;
#pragma unroll
            for (int j = 0; j < 4; ++j) {
                int seg = ws0 + j;
                uint32_t off = 16u * (uint32_t)(seg ^ rx);
                cp16(rb + off, Whp + g + seg * 8);
                if (nterm >= 2) cp16(rb + 16384 + off, Wlp + g + seg * 8);
            }
        }
        CP_COMMIT();
    };

    float d[2][4][4] = {};
    const int r8 = (lane & 7) + ((lane >> 3) & 1) * 8;   // 0..15 row-in-tile
    const int sh = lane >> 4;                            // 0/1 seg offset

    // ---- prologue: 2 chunks in flight ----
    loadc(0, 0);
    loadc(1, 1);

    for (int i = 0; i < 8; ++i) {
        if (i < 7) cp_wait<1>(); else cp_wait<0>();
        __syncthreads();

        // compute on stage i&1 (chunk = 64 k = 4 k16 groups)
        {
            const uint32_t aB  = sbase + (i & 1) * stage_b;
            const uint32_t bB  = aB + 8192;
            const uint32_t blB = aB + 24576;
            const uint32_t alB = aB + 40960;
#pragma unroll
            for (int ks = 0; ks < 4; ++ks) {
                uint32_t ah[2][4], al[2][4], bh[2][4], bl[2][4];
                const int seg = 2 * ks + sh;
#pragma unroll
                for (int mt = 0; mt < 2; ++mt) {
                    int row = wm * 32 + mt * 16 + r8;
                    int rx = row & 7;
                    ldmatrix4(ah[mt], aB + row * 128 + 16 * (seg ^ rx));
                    if (nterm >= 3)
                        ldmatrix4(al[mt], alB + row * 128 + 16 * (seg ^ rx));
                }
#pragma unroll
                for (int g = 0; g < 2; ++g) {
                    int nrow = wn * 32 + g * 16 + r8;
                    int rx = nrow & 7;
                    ldmatrix4(bh[g], bB + nrow * 128 + 16 * (seg ^ rx));
                    if (nterm >= 2)
                        ldmatrix4(bl[g], blB + nrow * 128 + 16 * (seg ^ rx));
                }
#pragma unroll
                for (int g = 0; g < 2; ++g)
#pragma unroll
                    for (int q = 0; q < 2; ++q) {
                        const int nt = g * 2 + q;
                        const uint32_t bh0 = bh[g][q], bh1 = bh[g][q + 2];
#pragma unroll
                        for (int mt = 0; mt < 2; ++mt) {
                            mma_f16(d[mt][nt], ah[mt], bh0, bh1);                    // hi*hi
                            if (nterm >= 2)
                                mma_f16(d[mt][nt], ah[mt], bl[g][q], bl[g][q + 2]);  // hi*lo
                            if (nterm >= 3)
                                mma_f16(d[mt][nt], al[mt], bh0, bh1);                // lo*hi
                        }
                    }
            }
        }

        __syncthreads();   // 2-stage: next load overwrites the stage just computed

        if (i + 2 < 8) loadc(i + 2, i & 1);
    }

    // ---- epilogue (C frag: lane row = lane/4 (+8), col = (lane%4)*2 (+1)) ----
    const int rql = lane >> 2;
    const int cql = (lane & 3) * 2;
#pragma unroll
    for (int mt = 0; mt < 2; ++mt) {
        int mbase = m0 + wm * 32 + mt * 16 + rql;
#pragma unroll
        for (int nt = 0; nt < 4; ++nt) {
            int n = n0 + wn * 32 + nt * 8 + cql;
            float2 bv = *(const float2*)&bias[n];
#pragma unroll
            for (int rr = 0; rr < 2; ++rr) {
                int m = mbase + rr * 8;
                float v0 = (d[mt][nt][rr * 2 + 0] + bv.x) * scale;
                float v1 = (d[mt][nt][rr * 2 + 1] + bv.y) * scale;
                int b = m >> 11, s = m & 2047;
                int h = n >> 6, dd = n & 63;
                if (mode == 0) {
                    // Q/K fp16 [b,h,s,d]
                    unsigned short* o16 = (unsigned short*)outv;
                    __half2 hv = __floats2half2_rn(v0, v1);
                    *(uint32_t*)&o16[(((size_t)(b * H_ + h)) * S_ + s) * 64 + dd] =
                        *reinterpret_cast<uint32_t*>(&hv);
                } else if (mode == 3) {
                    // V fp16 [b,h,d,s]
                    unsigned short* o16 = (unsigned short*)outv;
                    size_t rb = (((size_t)(b * H_ + h)) * DH_ + dd) * S_ + s;
                    o16[rb]      = __half_as_ushort(__float2half_rn(v0));
                    o16[rb + S_] = __half_as_ushort(__float2half_rn(v1));
                } else {
                    float2 v = make_float2(v0, v1);
                    *(float2*)&((float*)outv)[(size_t)m * 512 + n] = v;
                }
            }
        }
    }
}

// ============================================================================
// Tensor-core flash attention, fp16 S-phase + Ph*Vh PV phase. (validated R12)
//   CTA: 128q x 64k per tile, 8 warps x 16q.
//   Q,K fp16 [b,h,s,64] rows (128B). V fp16 [b,h,d,2048] rows.
//   Q pre-scaled by (1/sqrt(DH))*log2(e) -> exp == ex2.
// ============================================================================
#define AT_SQ   0
#define AT_SK   16384
#define AT_SV   (16384 + 2 * 8192)
#define AT_SMEM (16384 + 4 * 8192)     // 49152

__global__ __launch_bounds__(256) void attn_mma(
    const unsigned short* __restrict__ Qf, const unsigned short* __restrict__ Kf,
    const unsigned short* __restrict__ Vf, const int* __restrict__ lens,
    unsigned short* __restrict__ ctxh, unsigned short* __restrict__ ctxl)
{
    extern __shared__ __align__(16) char smem[];
    const uint32_t sb = smem_u32(smem);

    const int tid = threadIdx.x;
    const int lane = tid & 31;
    const int warp = tid >> 5;
    const int q0 = blockIdx.x * 128;
    const int h = blockIdx.y;
    const int b = blockIdx.z;
    const int len = lens[b];

    const size_t bh = (size_t)(b * H_ + h);
    const unsigned short* Qg = Qf + (bh * S_ + q0) * 64;
    const unsigned short* Kg = Kf + bh * S_ * 64;
    const unsigned short* Vg = Vf + bh * (size_t)DH_ * S_;

    const int r8 = (lane & 7) + ((lane >> 3) & 1) * 8;   // 0..15
    const int sh = lane >> 4;                            // 0/1
    const int u2 = (lane & 3) * 2;                       // col pair base
    const int rx = r8 & 7;

    // ---- load Q tile (128 rows x 128B), one commit group ----
#pragma unroll
    for (int j = 0; j < 4; ++j) {
        int idx = j * 256 + tid;
        int row = idx >> 3, seg = idx & 7;
        cp16(sb + AT_SQ + row * 128 + 16 * (seg ^ (row & 7)), Qg + (size_t)row * 64 + seg * 8);
    }
    CP_COMMIT();

    // ---- K/V tile loader (4 cp16/thread, one group) ----
    auto loadKV = [&](int kt0, int buf) {
        const uint32_t dk = sb + AT_SK + buf * 8192;
        const uint32_t dv = sb + AT_SV + buf * 8192;
#pragma unroll
        for (int j = 0; j < 2; ++j) {
            int idx = j * 256 + tid;
            int row = idx >> 3, seg = idx & 7;
            uint32_t off = row * 128 + 16 * (seg ^ (row & 7));
            cp16(dk + off, Kg + ((size_t)(kt0 + row)) * 64 + seg * 8);
            cp16(dv + off, Vg + (size_t)row * S_ + kt0 + seg * 8);
        }
        CP_COMMIT();
    };

    loadKV(0, 0);
    cp_wait<0>();
    __syncthreads();

    // ---- extract Q A-frags (register resident): qa[kg] ----
    uint32_t qa[4][4];
    {
        const int qrow = 16 * warp + r8;
        const uint32_t qb = sb + AT_SQ + qrow * 128;
#pragma unroll
        for (int kg = 0; kg < 4; ++kg)
            ldmatrix4(qa[kg], qb + 16 * ((2 * kg + sh) ^ rx));
    }

    float oacc[8][4] = {};
    float m0 = -1e30f, m1 = -1e30f, l0 = 0.f, l1 = 0.f;

    const int nkt = (len + 63) >> 6;

    for (int t = 0; t < nkt; ++t) {
        if (t + 1 < nkt) loadKV((t + 1) * 64, (t + 1) & 1);

        const uint32_t kb = sb + AT_SK + (t & 1) * 8192;
        const uint32_t vbuf = sb + AT_SV + (t & 1) * 8192;

        // ---- S = Q K^T (pure fp16) ----
        float sacc[8][4] = {};
#pragma unroll
        for (int kg = 0; kg < 4; ++kg) {
            const uint32_t off = 16u * (uint32_t)((2 * kg + sh) ^ rx);
#pragma unroll
            for (int g = 0; g < 4; ++g) {
                uint32_t kh[4];
                ldmatrix4(kh, kb + (16 * g + r8) * 128 + off);
#pragma unroll
                for (int q = 0; q < 2; ++q)
                    mma_f16(sacc[2 * g + q], qa[kg], kh[q], kh[q + 2]);
            }
        }

        // ---- mask tail keys ----
        const int kt0 = t * 64;
        if (kt0 + 64 > len) {
#pragma unroll
            for (int nt = 0; nt < 8; ++nt) {
                int c0 = kt0 + nt * 8 + u2;
                if (c0 >= len)     { sacc[nt][0] = -1e30f; sacc[nt][2] = -1e30f; }
                if (c0 + 1 >= len) { sacc[nt][1] = -1e30f; sacc[nt][3] = -1e30f; }
            }
        }

        // ---- online softmax (rows l/4 and l/4+8; quad shfl reductions) ----
        float mx0 = -1e30f, mx1 = -1e30f;
#pragma unroll
        for (int nt = 0; nt < 8; ++nt) {
            mx0 = fmaxf(mx0, fmaxf(sacc[nt][0], sacc[nt][1]));
            mx1 = fmaxf(mx1, fmaxf(sacc[nt][2], sacc[nt][3]));
        }
        mx0 = fmaxf(mx0, __shfl_xor_sync(0xffffffffu, mx0, 1));
        mx0 = fmaxf(mx0, __shfl_xor_sync(0xffffffffu, mx0, 2));
        mx1 = fmaxf(mx1, __shfl_xor_sync(0xffffffffu, mx1, 1));
        mx1 = fmaxf(mx1, __shfl_xor_sync(0xffffffffu, mx1, 2));

        const float mn0 = fmaxf(m0, mx0), mn1 = fmaxf(m1, mx1);
        const float e0 = ex2f(m0 - mn0), e1 = ex2f(m1 - mn1);
        m0 = mn0; m1 = mn1;

        float s0 = 0.f, s1 = 0.f;
#pragma unroll
        for (int nt = 0; nt < 8; ++nt) {
            float p;
            p = ex2f(sacc[nt][0] - mn0); sacc[nt][0] = p; s0 += p;
            p = ex2f(sacc[nt][1] - mn0); sacc[nt][1] = p; s0 += p;
            p = ex2f(sacc[nt][2] - mn1); sacc[nt][2] = p; s1 += p;
            p = ex2f(sacc[nt][3] - mn1); sacc[nt][3] = p; s1 += p;
        }
        s0 += __shfl_xor_sync(0xffffffffu, s0, 1);
        s0 += __shfl_xor_sync(0xffffffffu, s0, 2);
        s1 += __shfl_xor_sync(0xffffffffu, s1, 1);
        s1 += __shfl_xor_sync(0xffffffffu, s1, 2);
        l0 = l0 * e0 + s0;
        l1 = l1 * e1 + s1;

#pragma unroll
        for (int nt = 0; nt < 8; ++nt) {
            oacc[nt][0] *= e0; oacc[nt][1] *= e0;
            oacc[nt][2] *= e1; oacc[nt][3] *= e1;
        }

        // ---- O += Ph Vh (P fp16-rounded; softmax-bounded error) ----
#pragma unroll
        for (int u = 0; u < 4; ++u) {          // k16 subgroup
            const int g0 = 2 * u;
            uint32_t ph[4];
            __half2 t0 = __floats2half2_rn(sacc[g0][0], sacc[g0][1]);
            __half2 t1 = __floats2half2_rn(sacc[g0][2], sacc[g0][3]);
            __half2 t2 = __floats2half2_rn(sacc[g0 + 1][0], sacc[g0 + 1][1]);
            __half2 t3 = __floats2half2_rn(sacc[g0 + 1][2], sacc[g0 + 1][3]);
            ph[0] = *reinterpret_cast<uint32_t*>(&t0);
            ph[1] = *reinterpret_cast<uint32_t*>(&t1);
            ph[2] = *reinterpret_cast<uint32_t*>(&t2);
            ph[3] = *reinterpret_cast<uint32_t*>(&t3);

            const uint32_t off = 16u * (uint32_t)((2 * u + sh) ^ rx);
#pragma unroll
            for (int dt = 0; dt < 4; ++dt) {
                uint32_t vh[4];
                ldmatrix4(vh, vbuf + (16 * dt + r8) * 128 + off);
#pragma unroll
                for (int q = 0; q < 2; ++q)
                    mma_f16(oacc[2 * dt + q], ph, vh[q], vh[q + 2]);
            }
        }

        if (t + 1 < nkt) cp_wait<0>();
        __syncthreads();
    }

    // ---- write compact ctx hi/lo [b*S+q, 512] ----
    const float inv0 = 1.0f / l0;
    const float inv1 = 1.0f / l1;
    const int qg0 = q0 + 16 * warp + (lane >> 2);
    const int qg1 = qg0 + 8;
    const size_t rb0 = ((size_t)b * S_ + qg0) * 512;
    const size_t rb1 = ((size_t)b * S_ + qg1) * 512;
#pragma unroll
    for (int nt = 0; nt < 8; ++nt) {
        int n = h * 64 + nt * 8 + u2;
        uint32_t hi2, lo2;
        hsplit2(oacc[nt][0] * inv0, oacc[nt][1] * inv0, hi2, lo2);
        *(uint32_t*)&ctxh[rb0 + n] = hi2;
        *(uint32_t*)&ctxl[rb0 + n] = lo2;
        hsplit2(oacc[nt][2] * inv1, oacc[nt][3] * inv1, hi2, lo2);
        *(uint32_t*)&ctxh[rb1 + n] = hi2;
        *(uint32_t*)&ctxl[rb1 + n] = lo2;
    }
}

// ---------------------------------------------------------------------------

extern "C" void kernel_launch(void* const* d_in, const int* in_sizes, int n_in,
                              void* d_out, int out_size)
{
    const float* x_Q = (const float*)d_in[0];
    const float* x_K = (const float*)d_in[1];
    const float* x_V = (const float*)d_in[2];
    const float* Wq  = (const float*)d_in[3];
    const float* bq  = (const float*)d_in[4];
    const float* Wk  = (const float*)d_in[5];
    const float* bk  = (const float*)d_in[6];
    const float* Wv  = (const float*)d_in[7];
    const float* bv  = (const float*)d_in[8];
    const float* Wo  = (const float*)d_in[9];
    const float* bo  = (const float*)d_in[10];
    const int*   lens = (const int*)d_in[11];
    float* out = (float*)d_out;

    unsigned short *xQh, *xKh, *xVh, *Wqh, *Wkh, *Wvh, *Wvl, *Woh, *Wol;
    unsigned short *ctxh, *ctxl, *Qf, *Kf, *Vf;
    cudaGetSymbolAddress((void**)&xQh, g_xQh);
    cudaGetSymbolAddress((void**)&xKh, g_xKh);
    cudaGetSymbolAddress((void**)&xVh, g_xVh);
    cudaGetSymbolAddress((void**)&Wqh, g_Wqh);
    cudaGetSymbolAddress((void**)&Wkh, g_Wkh);
    cudaGetSymbolAddress((void**)&Wvh, g_Wvh);
    cudaGetSymbolAddress((void**)&Wvl, g_Wvl);
    cudaGetSymbolAddress((void**)&Woh, g_Woh);
    cudaGetSymbolAddress((void**)&Wol, g_Wol);
    cudaGetSymbolAddress((void**)&ctxh, g_ctxh);
    cudaGetSymbolAddress((void**)&ctxl, g_ctxl);
    cudaGetSymbolAddress((void**)&Qf,  g_Qf);
    cudaGetSymbolAddress((void**)&Kf,  g_Kf);
    cudaGetSymbolAddress((void**)&Vf,  g_Vf);

    cudaFuncSetAttribute(proj_mma, cudaFuncAttributeMaxDynamicSharedMemorySize, PJ_SMEM_MAX);
    cudaFuncSetAttribute(attn_mma, cudaFuncAttributeMaxDynamicSharedMemorySize, AT_SMEM);

    // ---- pack passes (2 launches) ----
    {
        PackArgs px;
        px.src[0] = x_Q; px.dh[0] = xQh; px.dl[0] = nullptr;
        px.src[1] = x_K; px.dh[1] = xKh; px.dl[1] = nullptr;
        px.src[2] = x_V; px.dh[2] = xVh; px.dl[2] = nullptr;
        px.src[3] = x_Q; px.dh[3] = xQh; px.dl[3] = nullptr;   // unused lane
        px.n = M_ * D_;
        dim3 gx((M_ * D_ / 8 + 255) / 256, 3);
        pack_h16<<<gx, 256>>>(px);

        PackArgs pw;
        pw.src[0] = Wq; pw.dh[0] = Wqh; pw.dl[0] = nullptr;
        pw.src[1] = Wk; pw.dh[1] = Wkh; pw.dl[1] = nullptr;
        pw.src[2] = Wv; pw.dh[2] = Wvh; pw.dl[2] = Wvl;
        pw.src[3] = Wo; pw.dh[3] = Woh; pw.dl[3] = Wol;
        pw.n = D_ * D_;
        dim3 gw((D_ * D_ / 8 + 255) / 256, 4);
        pack_h16<<<gw, 256>>>(pw);
    }

    // scale = 1/sqrt(DH) * log2(e), folded into Q projection (incl. bias)
    const float qscale = 0.125f * 1.4426950408889634f;

    // ---- batched Q/K/V projections (one launch, 40KB stage x2 -> 2 CTA/SM) ----
    {
        ProjArgs pa;
        pa.Ah[0] = xQh; pa.Al[0] = nullptr; pa.Wh[0] = Wqh; pa.Wl[0] = nullptr;
        pa.bias[0] = bq; pa.out[0] = Qf; pa.scale[0] = qscale; pa.mode[0] = 0; pa.nterm[0] = 1;
        pa.Ah[1] = xKh; pa.Al[1] = nullptr; pa.Wh[1] = Wkh; pa.Wl[1] = nullptr;
        pa.bias[1] = bk; pa.out[1] = Kf; pa.scale[1] = 1.0f;   pa.mode[1] = 0; pa.nterm[1] = 1;
        pa.Ah[2] = xVh; pa.Al[2] = nullptr; pa.Wh[2] = Wvh; pa.Wl[2] = Wvl;
        pa.bias[2] = bv; pa.out[2] = Vf; pa.scale[2] = 1.0f;   pa.mode[2] = 3; pa.nterm[2] = 2;
        dim3 g(D_ / 128, M_ / 64, 3);
        proj_mma<<<g, 256, 2 * 40960>>>(pa, 40960);
    }

    dim3 gattn(S_ / 128, H_, B_);
    attn_mma<<<gattn, 256, AT_SMEM>>>(Qf, Kf, Vf, lens, ctxh, ctxl);

    // ---- final projection (3-term exact, 48KB stage x2 -> 2 CTA/SM) ----
    {
        ProjArgs pa;
        pa.Ah[0] = ctxh; pa.Al[0] = ctxl; pa.Wh[0] = Woh; pa.Wl[0] = Wol;
        pa.bias[0] = bo; pa.out[0] = out; pa.scale[0] = 1.0f; pa.mode[0] = 2; pa.nterm[0] = 3;
        pa.Ah[1] = ctxh; pa.Al[1] = ctxl; pa.Wh[1] = Woh; pa.Wl[1] = Wol;
        pa.bias[1] = bo; pa.out[1] = out; pa.scale[1] = 1.0f; pa.mode[1] = 2; pa.nterm[1] = 3;
        pa.Ah[2] = ctxh; pa.Al[2] = ctxl; pa.Wh[2] = Woh; pa.Wl[2] = Wol;
        pa.bias[2] = bo; pa.out[2] = out; pa.scale[2] = 1.0f; pa.mode[2] = 2; pa.nterm[2] = 3;
        dim3 g(D_ / 128, M_ / 64, 1);
        proj_mma<<<g, 256, 2 * 49152>>>(pa, 49152);
    }
}

// round 15
// speedup vs baseline: 1.1178x; 1.1178x over previous
#include <cuda_runtime.h>
#include <cuda_fp16.h>
#include <cstdint>

// Problem constants (fixed by the reference)
#define B_  8
#define S_  2048
#define D_  512
#define H_  8
#define DH_ 64
#define M_  (B_ * S_)          // 16384 rows for all projections

// Scratch (allocation-free rule: __device__ globals)
// Compact per-plane fp16 streams, row-major [rows, 512]
__device__ unsigned short g_xQh[M_ * D_];
__device__ unsigned short g_xKh[M_ * D_];
__device__ unsigned short g_xVh[M_ * D_];
__device__ unsigned short g_Wqh[D_ * D_];
__device__ unsigned short g_Wkh[D_ * D_];
__device__ unsigned short g_Wvh[D_ * D_];
__device__ unsigned short g_Wvl[D_ * D_];
__device__ unsigned short g_Woh[D_ * D_];
__device__ unsigned short g_Wol[D_ * D_];
__device__ unsigned short g_ctxh[M_ * D_];               // ctx fp16 (hi only)
// Attention operands, pure fp16:
__device__ unsigned short g_Qf[B_ * H_ * S_ * DH_];      // [b,h,s,d] fp16
__device__ unsigned short g_Kf[B_ * H_ * S_ * DH_];      // [b,h,s,d] fp16
__device__ unsigned short g_Vf[B_ * H_ * DH_ * S_];      // [b,h,d,s] fp16

__device__ __forceinline__ float ex2f(float x) {
    float y;
    asm("ex2.approx.f32 %0, %1;" : "=f"(y) : "f"(x));
    return y;
}

__device__ __forceinline__ uint32_t smem_u32(const void* p) {
    uint32_t a;
    asm("{ .reg .u64 t; cvta.to.shared.u64 t, %1; cvt.u32.u64 %0, t; }" : "=r"(a) : "l"(p));
    return a;
}

__device__ __forceinline__ void cp16(uint32_t dst, const void* src) {
    asm volatile("cp.async.cg.shared.global [%0], [%1], 16;" :: "r"(dst), "l"(src) : "memory");
}
#define CP_COMMIT() asm volatile("cp.async.commit_group;" ::: "memory")
template <int N>
__device__ __forceinline__ void cp_wait() {
    asm volatile("cp.async.wait_group %0;" :: "n"(N) : "memory");
}

__device__ __forceinline__ void ldmatrix4(uint32_t* r, uint32_t addr) {
    asm volatile("ldmatrix.sync.aligned.m8n8.x4.shared.b16 {%0,%1,%2,%3}, [%4];"
                 : "=r"(r[0]), "=r"(r[1]), "=r"(r[2]), "=r"(r[3]) : "r"(addr));
}

__device__ __forceinline__ void mma_f16(float* d, const uint32_t* a,
                                        uint32_t b0, uint32_t b1) {
    asm volatile(
        "mma.sync.aligned.m16n8k16.row.col.f32.f16.f16.f32 "
        "{%0,%1,%2,%3}, {%4,%5,%6,%7}, {%8,%9}, {%0,%1,%2,%3};"
        : "+f"(d[0]), "+f"(d[1]), "+f"(d[2]), "+f"(d[3])
        : "r"(a[0]), "r"(a[1]), "r"(a[2]), "r"(a[3]), "r"(b0), "r"(b1));
}

// fp32 -> fp16 hi/lo bits (scalar)
__device__ __forceinline__ void hsplit(float f, unsigned short& hi, unsigned short& lo) {
    __half h = __float2half_rn(f);
    float hf = __half2float(h);
    __half l = __float2half_rn(f - hf);
    hi = __half_as_ushort(h);
    lo = __half_as_ushort(l);
}

// ============================================================================
// Pack pass: fp32 row-major -> compact fp16 hi stream (+ optional lo stream)
// ============================================================================
struct PackArgs {
    const float*    src[4];
    unsigned short* dh[4];
    unsigned short* dl[4];     // null -> skip lo
    int n;
};

__global__ __launch_bounds__(256) void pack_h16(PackArgs pa)
{
    const float* src = pa.src[blockIdx.y];
    unsigned short* dh = pa.dh[blockIdx.y];
    unsigned short* dl = pa.dl[blockIdx.y];
    int e = (blockIdx.x * 256 + threadIdx.x) * 8;
    if (e >= pa.n) return;

    float4 v0 = *(const float4*)(src + e);
    float4 v1 = *(const float4*)(src + e + 4);
    unsigned short hb[8], lb[8];
    hsplit(v0.x, hb[0], lb[0]); hsplit(v0.y, hb[1], lb[1]);
    hsplit(v0.z, hb[2], lb[2]); hsplit(v0.w, hb[3], lb[3]);
    hsplit(v1.x, hb[4], lb[4]); hsplit(v1.y, hb[5], lb[5]);
    hsplit(v1.z, hb[6], lb[6]); hsplit(v1.w, hb[7], lb[7]);
    *(uint4*)(dh + e) = *(uint4*)hb;
    if (dl) *(uint4*)(dl + e) = *(uint4*)lb;
}

// ============================================================================
// Split-fp16 projection GEMM (R12 shape), compact streams, cp.async 4-stage.
//   C = A @ W^T;  nterm: 1 = Ah*Wh;  2 = Ah*Wh + Ah*Wl (A fp16-rounded).
//   CTA: 128m x 128n, 512 threads (16 warps, 32x32 warp tiles), chunk = 64 k.
//   Stage layout: [Ah 16KB][Wh 16KB][Wl 16KB] = 48KB; 4 stages, 3 in flight.
//   mode 0: fp16 [b,h,s,d] (Q/K)   mode 2: fp32 [M,512]   mode 3: fp16 [b,h,d,s] (V)
// ============================================================================
struct ProjArgs {
    const unsigned short* Ah[3];
    const unsigned short* Wh[3];
    const unsigned short* Wl[3];
    const float* bias[3];
    void* out[3];
    float scale[3];
    int mode[3];
    int nterm[3];
};

#define PJ_STAGE_B 49152
#define PJ_SMEM_B  (4 * PJ_STAGE_B)   // 196608

__global__ __launch_bounds__(512) void proj_mma(ProjArgs pa)
{
    const int z = blockIdx.z;
    const unsigned short* Ahp = pa.Ah[z];
    const unsigned short* Whp = pa.Wh[z];
    const unsigned short* Wlp = pa.Wl[z];
    const float* bias = pa.bias[z];
    void* outv = pa.out[z];
    const float scale = pa.scale[z];
    const int mode = pa.mode[z];
    const int nterm = pa.nterm[z];

    extern __shared__ __align__(16) char smem[];
    const uint32_t sbase = smem_u32(smem);

    const int tid = threadIdx.x;
    const int lane = tid & 31;
    const int warp = tid >> 5;
    const int wm = warp >> 2;          // 0..3
    const int wn = warp & 3;           // 0..3
    const int m0 = blockIdx.y * 128;
    const int n0 = blockIdx.x * 128;

    const int lrow = tid >> 2;         // 0..127 (loader row)
    const int ls0  = (tid & 3) * 2;    // first 16B seg (of 8 per 128B chunk-row)

    auto loadc = [&](int c, int st) {
        const unsigned short* As = Ahp + (size_t)(m0 + lrow) * 512 + c * 64;
        const unsigned short* Ws = Whp + (size_t)(n0 + lrow) * 512 + c * 64;
        const unsigned short* Wl = Wlp + (size_t)(n0 + lrow) * 512 + c * 64;
        const uint32_t base = sbase + st * PJ_STAGE_B + lrow * 128;
        const int rx = lrow & 7;
#pragma unroll
        for (int j = 0; j < 2; ++j) {
            int seg = ls0 + j;
            uint32_t off = 16u * (uint32_t)(seg ^ rx);
            cp16(base + off,         As + seg * 8);
            cp16(base + 16384 + off, Ws + seg * 8);
            if (nterm >= 2) cp16(base + 32768 + off, Wl + seg * 8);
        }
        CP_COMMIT();
    };

    float d[2][4][4] = {};
    const int r8 = (lane & 7) + ((lane >> 3) & 1) * 8;   // 0..15 row-in-tile
    const int sh = lane >> 4;                            // 0/1 seg offset

    // ---- prologue: 3 chunks in flight ----
    loadc(0, 0);
    loadc(1, 1);
    loadc(2, 2);

    for (int i = 0; i < 8; ++i) {
        if (i <= 5) cp_wait<2>();
        else if (i == 6) cp_wait<1>();
        else cp_wait<0>();
        __syncthreads();

        // compute on stage i&3 (chunk = 64 k = 4 k16 groups)
        {
            const uint32_t aB  = sbase + (i & 3) * PJ_STAGE_B;
            const uint32_t bB  = aB + 16384;
            const uint32_t blB = aB + 32768;
#pragma unroll
            for (int ks = 0; ks < 4; ++ks) {
                uint32_t ah[2][4], bh[2][4], bl[2][4];
                const int seg = 2 * ks + sh;
#pragma unroll
                for (int mt = 0; mt < 2; ++mt) {
                    int row = wm * 32 + mt * 16 + r8;
                    int rx = row & 7;
                    ldmatrix4(ah[mt], aB + row * 128 + 16 * (seg ^ rx));
                }
#pragma unroll
                for (int g = 0; g < 2; ++g) {
                    int nrow = wn * 32 + g * 16 + r8;
                    int rx = nrow & 7;
                    ldmatrix4(bh[g], bB + nrow * 128 + 16 * (seg ^ rx));
                    if (nterm >= 2)
                        ldmatrix4(bl[g], blB + nrow * 128 + 16 * (seg ^ rx));
                }
#pragma unroll
                for (int g = 0; g < 2; ++g)
#pragma unroll
                    for (int q = 0; q < 2; ++q) {
                        const int nt = g * 2 + q;
                        const uint32_t bh0 = bh[g][q], bh1 = bh[g][q + 2];
#pragma unroll
                        for (int mt = 0; mt < 2; ++mt) {
                            mma_f16(d[mt][nt], ah[mt], bh0, bh1);                    // hi*hi
                            if (nterm >= 2)
                                mma_f16(d[mt][nt], ah[mt], bl[g][q], bl[g][q + 2]);  // hi*lo
                        }
                    }
            }
        }

        if (i + 3 < 8) loadc(i + 3, (i + 3) & 3);
    }

    // ---- epilogue (C frag: lane row = lane/4 (+8), col = (lane%4)*2 (+1)) ----
    const int rql = lane >> 2;
    const int cql = (lane & 3) * 2;
#pragma unroll
    for (int mt = 0; mt < 2; ++mt) {
        int mbase = m0 + wm * 32 + mt * 16 + rql;
#pragma unroll
        for (int nt = 0; nt < 4; ++nt) {
            int n = n0 + wn * 32 + nt * 8 + cql;
            float2 bv = *(const float2*)&bias[n];
#pragma unroll
            for (int rr = 0; rr < 2; ++rr) {
                int m = mbase + rr * 8;
                float v0 = (d[mt][nt][rr * 2 + 0] + bv.x) * scale;
                float v1 = (d[mt][nt][rr * 2 + 1] + bv.y) * scale;
                int b = m >> 11, s = m & 2047;
                int h = n >> 6, dd = n & 63;
                if (mode == 0) {
                    // Q/K fp16 [b,h,s,d]
                    unsigned short* o16 = (unsigned short*)outv;
                    __half2 hv = __floats2half2_rn(v0, v1);
                    *(uint32_t*)&o16[(((size_t)(b * H_ + h)) * S_ + s) * 64 + dd] =
                        *reinterpret_cast<uint32_t*>(&hv);
                } else if (mode == 3) {
                    // V fp16 [b,h,d,s]
                    unsigned short* o16 = (unsigned short*)outv;
                    size_t rb = (((size_t)(b * H_ + h)) * DH_ + dd) * S_ + s;
                    o16[rb]      = __half_as_ushort(__float2half_rn(v0));
                    o16[rb + S_] = __half_as_ushort(__float2half_rn(v1));
                } else {
                    float2 v = make_float2(v0, v1);
                    *(float2*)&((float*)outv)[(size_t)m * 512 + n] = v;
                }
            }
        }
    }
}

// ============================================================================
// Tensor-core flash attention, fp16 S-phase + Ph*Vh PV phase. (validated R12)
//   CTA: 128q x 64k per tile, 8 warps x 16q.
//   Q,K fp16 [b,h,s,64] rows (128B). V fp16 [b,h,d,2048] rows.
//   Q pre-scaled by (1/sqrt(DH))*log2(e) -> exp == ex2.
//   Epilogue writes fp16 ctx (hi only).
// ============================================================================
#define AT_SQ   0
#define AT_SK   16384
#define AT_SV   (16384 + 2 * 8192)
#define AT_SMEM (16384 + 4 * 8192)     // 49152

__global__ __launch_bounds__(256) void attn_mma(
    const unsigned short* __restrict__ Qf, const unsigned short* __restrict__ Kf,
    const unsigned short* __restrict__ Vf, const int* __restrict__ lens,
    unsigned short* __restrict__ ctxh)
{
    extern __shared__ __align__(16) char smem[];
    const uint32_t sb = smem_u32(smem);

    const int tid = threadIdx.x;
    const int lane = tid & 31;
    const int warp = tid >> 5;
    const int q0 = blockIdx.x * 128;
    const int h = blockIdx.y;
    const int b = blockIdx.z;
    const int len = lens[b];

    const size_t bh = (size_t)(b * H_ + h);
    const unsigned short* Qg = Qf + (bh * S_ + q0) * 64;
    const unsigned short* Kg = Kf + bh * S_ * 64;
    const unsigned short* Vg = Vf + bh * (size_t)DH_ * S_;

    const int r8 = (lane & 7) + ((lane >> 3) & 1) * 8;   // 0..15
    const int sh = lane >> 4;                            // 0/1
    const int u2 = (lane & 3) * 2;                       // col pair base
    const int rx = r8 & 7;

    // ---- load Q tile (128 rows x 128B), one commit group ----
#pragma unroll
    for (int j = 0; j < 4; ++j) {
        int idx = j * 256 + tid;
        int row = idx >> 3, seg = idx & 7;
        cp16(sb + AT_SQ + row * 128 + 16 * (seg ^ (row & 7)), Qg + (size_t)row * 64 + seg * 8);
    }
    CP_COMMIT();

    // ---- K/V tile loader (4 cp16/thread, one group) ----
    auto loadKV = [&](int kt0, int buf) {
        const uint32_t dk = sb + AT_SK + buf * 8192;
        const uint32_t dv = sb + AT_SV + buf * 8192;
#pragma unroll
        for (int j = 0; j < 2; ++j) {
            int idx = j * 256 + tid;
            int row = idx >> 3, seg = idx & 7;
            uint32_t off = row * 128 + 16 * (seg ^ (row & 7));
            cp16(dk + off, Kg + ((size_t)(kt0 + row)) * 64 + seg * 8);
            cp16(dv + off, Vg + (size_t)row * S_ + kt0 + seg * 8);
        }
        CP_COMMIT();
    };

    loadKV(0, 0);
    cp_wait<0>();
    __syncthreads();

    // ---- extract Q A-frags (register resident): qa[kg] ----
    uint32_t qa[4][4];
    {
        const int qrow = 16 * warp + r8;
        const uint32_t qb = sb + AT_SQ + qrow * 128;
#pragma unroll
        for (int kg = 0; kg < 4; ++kg)
            ldmatrix4(qa[kg], qb + 16 * ((2 * kg + sh) ^ rx));
    }

    float oacc[8][4] = {};
    float m0 = -1e30f, m1 = -1e30f, l0 = 0.f, l1 = 0.f;

    const int nkt = (len + 63) >> 6;

    for (int t = 0; t < nkt; ++t) {
        if (t + 1 < nkt) loadKV((t + 1) * 64, (t + 1) & 1);

        const uint32_t kb = sb + AT_SK + (t & 1) * 8192;
        const uint32_t vbuf = sb + AT_SV + (t & 1) * 8192;

        // ---- S = Q K^T (pure fp16) ----
        float sacc[8][4] = {};
#pragma unroll
        for (int kg = 0; kg < 4; ++kg) {
            const uint32_t off = 16u * (uint32_t)((2 * kg + sh) ^ rx);
#pragma unroll
            for (int g = 0; g < 4; ++g) {
                uint32_t kh[4];
                ldmatrix4(kh, kb + (16 * g + r8) * 128 + off);
#pragma unroll
                for (int q = 0; q < 2; ++q)
                    mma_f16(sacc[2 * g + q], qa[kg], kh[q], kh[q + 2]);
            }
        }

        // ---- mask tail keys ----
        const int kt0 = t * 64;
        if (kt0 + 64 > len) {
#pragma unroll
            for (int nt = 0; nt < 8; ++nt) {
                int c0 = kt0 + nt * 8 + u2;
                if (c0 >= len)     { sacc[nt][0] = -1e30f; sacc[nt][2] = -1e30f; }
                if (c0 + 1 >= len) { sacc[nt][1] = -1e30f; sacc[nt][3] = -1e30f; }
            }
        }

        // ---- online softmax (rows l/4 and l/4+8; quad shfl reductions) ----
        float mx0 = -1e30f, mx1 = -1e30f;
#pragma unroll
        for (int nt = 0; nt < 8; ++nt) {
            mx0 = fmaxf(mx0, fmaxf(sacc[nt][0], sacc[nt][1]));
            mx1 = fmaxf(mx1, fmaxf(sacc[nt][2], sacc[nt][3]));
        }
        mx0 = fmaxf(mx0, __shfl_xor_sync(0xffffffffu, mx0, 1));
        mx0 = fmaxf(mx0, __shfl_xor_sync(0xffffffffu, mx0, 2));
        mx1 = fmaxf(mx1, __shfl_xor_sync(0xffffffffu, mx1, 1));
        mx1 = fmaxf(mx1, __shfl_xor_sync(0xffffffffu, mx1, 2));

        const float mn0 = fmaxf(m0, mx0), mn1 = fmaxf(m1, mx1);
        const float e0 = ex2f(m0 - mn0), e1 = ex2f(m1 - mn1);
        m0 = mn0; m1 = mn1;

        float s0 = 0.f, s1 = 0.f;
#pragma unroll
        for (int nt = 0; nt < 8; ++nt) {
            float p;
            p = ex2f(sacc[nt][0] - mn0); sacc[nt][0] = p; s0 += p;
            p = ex2f(sacc[nt][1] - mn0); sacc[nt][1] = p; s0 += p;
            p = ex2f(sacc[nt][2] - mn1); sacc[nt][2] = p; s1 += p;
            p = ex2f(sacc[nt][3] - mn1); sacc[nt][3] = p; s1 += p;
        }
        s0 += __shfl_xor_sync(0xffffffffu, s0, 1);
        s0 += __shfl_xor_sync(0xffffffffu, s0, 2);
        s1 += __shfl_xor_sync(0xffffffffu, s1, 1);
        s1 += __shfl_xor_sync(0xffffffffu, s1, 2);
        l0 = l0 * e0 + s0;
        l1 = l1 * e1 + s1;

#pragma unroll
        for (int nt = 0; nt < 8; ++nt) {
            oacc[nt][0] *= e0; oacc[nt][1] *= e0;
            oacc[nt][2] *= e1; oacc[nt][3] *= e1;
        }

        // ---- O += Ph Vh (P fp16-rounded; softmax-bounded error) ----
#pragma unroll
        for (int u = 0; u < 4; ++u) {          // k16 subgroup
            const int g0 = 2 * u;
            uint32_t ph[4];
            __half2 t0 = __floats2half2_rn(sacc[g0][0], sacc[g0][1]);
            __half2 t1 = __floats2half2_rn(sacc[g0][2], sacc[g0][3]);
            __half2 t2 = __floats2half2_rn(sacc[g0 + 1][0], sacc[g0 + 1][1]);
            __half2 t3 = __floats2half2_rn(sacc[g0 + 1][2], sacc[g0 + 1][3]);
            ph[0] = *reinterpret_cast<uint32_t*>(&t0);
            ph[1] = *reinterpret_cast<uint32_t*>(&t1);
            ph[2] = *reinterpret_cast<uint32_t*>(&t2);
            ph[3] = *reinterpret_cast<uint32_t*>(&t3);

            const uint32_t off = 16u * (uint32_t)((2 * u + sh) ^ rx);
#pragma unroll
            for (int dt = 0; dt < 4; ++dt) {
                uint32_t vh[4];
                ldmatrix4(vh, vbuf + (16 * dt + r8) * 128 + off);
#pragma unroll
                for (int q = 0; q < 2; ++q)
                    mma_f16(oacc[2 * dt + q], ph, vh[q], vh[q + 2]);
            }
        }

        if (t + 1 < nkt) cp_wait<0>();
        __syncthreads();
    }

    // ---- write fp16 ctx (hi only) [b*S+q, 512] ----
    const float inv0 = 1.0f / l0;
    const float inv1 = 1.0f / l1;
    const int qg0 = q0 + 16 * warp + (lane >> 2);
    const int qg1 = qg0 + 8;
    const size_t rb0 = ((size_t)b * S_ + qg0) * 512;
    const size_t rb1 = ((size_t)b * S_ + qg1) * 512;
#pragma unroll
    for (int nt = 0; nt < 8; ++nt) {
        int n = h * 64 + nt * 8 + u2;
        __half2 hv0 = __floats2half2_rn(oacc[nt][0] * inv0, oacc[nt][1] * inv0);
        __half2 hv1 = __floats2half2_rn(oacc[nt][2] * inv1, oacc[nt][3] * inv1);
        *(uint32_t*)&ctxh[rb0 + n] = *reinterpret_cast<uint32_t*>(&hv0);
        *(uint32_t*)&ctxh[rb1 + n] = *reinterpret_cast<uint32_t*>(&hv1);
    }
}

// ---------------------------------------------------------------------------

extern "C" void kernel_launch(void* const* d_in, const int* in_sizes, int n_in,
                              void* d_out, int out_size)
{
    const float* x_Q = (const float*)d_in[0];
    const float* x_K = (const float*)d_in[1];
    const float* x_V = (const float*)d_in[2];
    const float* Wq  = (const float*)d_in[3];
    const float* bq  = (const float*)d_in[4];
    const float* Wk  = (const float*)d_in[5];
    const float* bk  = (const float*)d_in[6];
    const float* Wv  = (const float*)d_in[7];
    const float* bv  = (const float*)d_in[8];
    const float* Wo  = (const float*)d_in[9];
    const float* bo  = (const float*)d_in[10];
    const int*   lens = (const int*)d_in[11];
    float* out = (float*)d_out;

    unsigned short *xQh, *xKh, *xVh, *Wqh, *Wkh, *Wvh, *Wvl, *Woh, *Wol;
    unsigned short *ctxh, *Qf, *Kf, *Vf;
    cudaGetSymbolAddress((void**)&xQh, g_xQh);
    cudaGetSymbolAddress((void**)&xKh, g_xKh);
    cudaGetSymbolAddress((void**)&xVh, g_xVh);
    cudaGetSymbolAddress((void**)&Wqh, g_Wqh);
    cudaGetSymbolAddress((void**)&Wkh, g_Wkh);
    cudaGetSymbolAddress((void**)&Wvh, g_Wvh);
    cudaGetSymbolAddress((void**)&Wvl, g_Wvl);
    cudaGetSymbolAddress((void**)&Woh, g_Woh);
    cudaGetSymbolAddress((void**)&Wol, g_Wol);
    cudaGetSymbolAddress((void**)&ctxh, g_ctxh);
    cudaGetSymbolAddress((void**)&Qf,  g_Qf);
    cudaGetSymbolAddress((void**)&Kf,  g_Kf);
    cudaGetSymbolAddress((void**)&Vf,  g_Vf);

    cudaFuncSetAttribute(proj_mma, cudaFuncAttributeMaxDynamicSharedMemorySize, PJ_SMEM_B);
    cudaFuncSetAttribute(attn_mma, cudaFuncAttributeMaxDynamicSharedMemorySize, AT_SMEM);

    // ---- pack passes (2 launches) ----
    {
        PackArgs px;
        px.src[0] = x_Q; px.dh[0] = xQh; px.dl[0] = nullptr;
        px.src[1] = x_K; px.dh[1] = xKh; px.dl[1] = nullptr;
        px.src[2] = x_V; px.dh[2] = xVh; px.dl[2] = nullptr;
        px.src[3] = x_Q; px.dh[3] = xQh; px.dl[3] = nullptr;   // unused lane
        px.n = M_ * D_;
        dim3 gx((M_ * D_ / 8 + 255) / 256, 3);
        pack_h16<<<gx, 256>>>(px);

        PackArgs pw;
        pw.src[0] = Wq; pw.dh[0] = Wqh; pw.dl[0] = nullptr;
        pw.src[1] = Wk; pw.dh[1] = Wkh; pw.dl[1] = nullptr;
        pw.src[2] = Wv; pw.dh[2] = Wvh; pw.dl[2] = Wvl;
        pw.src[3] = Wo; pw.dh[3] = Woh; pw.dl[3] = Wol;
        pw.n = D_ * D_;
        dim3 gw((D_ * D_ / 8 + 255) / 256, 4);
        pack_h16<<<gw, 256>>>(pw);
    }

    // scale = 1/sqrt(DH) * log2(e), folded into Q projection (incl. bias)
    const float qscale = 0.125f * 1.4426950408889634f;

    // ---- batched Q/K/V projections (one launch, 48KB stage x4) ----
    {
        ProjArgs pa;
        pa.Ah[0] = xQh; pa.Wh[0] = Wqh; pa.Wl[0] = nullptr;
        pa.bias[0] = bq; pa.out[0] = Qf; pa.scale[0] = qscale; pa.mode[0] = 0; pa.nterm[0] = 1;
        pa.Ah[1] = xKh; pa.Wh[1] = Wkh; pa.Wl[1] = nullptr;
        pa.bias[1] = bk; pa.out[1] = Kf; pa.scale[1] = 1.0f;   pa.mode[1] = 0; pa.nterm[1] = 1;
        pa.Ah[2] = xVh; pa.Wh[2] = Wvh; pa.Wl[2] = Wvl;
        pa.bias[2] = bv; pa.out[2] = Vf; pa.scale[2] = 1.0f;   pa.mode[2] = 3; pa.nterm[2] = 2;
        dim3 g(D_ / 128, M_ / 128, 3);
        proj_mma<<<g, 512, PJ_SMEM_B>>>(pa);
    }

    dim3 gattn(S_ / 128, H_, B_);
    attn_mma<<<gattn, 256, AT_SMEM>>>(Qf, Kf, Vf, lens, ctxh);

    // ---- final projection (2-term: ctx fp16-rounded, W exact) ----
    {
        ProjArgs pa;
        pa.Ah[0] = ctxh; pa.Wh[0] = Woh; pa.Wl[0] = Wol;
        pa.bias[0] = bo; pa.out[0] = out; pa.scale[0] = 1.0f; pa.mode[0] = 2; pa.nterm[0] = 2;
        pa.Ah[1] = ctxh; pa.Wh[1] = Woh; pa.Wl[1] = Wol;
        pa.bias[1] = bo; pa.out[1] = out; pa.scale[1] = 1.0f; pa.mode[1] = 2; pa.nterm[1] = 2;
        pa.Ah[2] = ctxh; pa.Wh[2] = Woh; pa.Wl[2] = Wol;
        pa.bias[2] = bo; pa.out[2] = out; pa.scale[2] = 1.0f; pa.mode[2] = 2; pa.nterm[2] = 2;
        dim3 g(D_ / 128, M_ / 128, 1);
        proj_mma<<<g, 512, PJ_SMEM_B>>>(pa);
    }
}

// round 16
// speedup vs baseline: 1.1257x; 1.0070x over previous
#include <cuda_runtime.h>
#include <cuda_fp16.h>
#include <cstdint>

// Problem constants (fixed by the reference)
#define B_  8
#define S_  2048
#define D_  512
#define H_  8
#define DH_ 64
#define M_  (B_ * S_)          // 16384 rows for all projections

// Scratch (allocation-free rule: __device__ globals)
// Compact per-plane fp16 streams, row-major [rows, 512]
__device__ unsigned short g_xQh[M_ * D_];
__device__ unsigned short g_xKh[M_ * D_];
__device__ unsigned short g_xVh[M_ * D_];
__device__ unsigned short g_Wqh[D_ * D_];
__device__ unsigned short g_Wkh[D_ * D_];
__device__ unsigned short g_Wvh[D_ * D_];
__device__ unsigned short g_Wvl[D_ * D_];
__device__ unsigned short g_Woh[D_ * D_];
__device__ unsigned short g_Wol[D_ * D_];
__device__ unsigned short g_ctxh[M_ * D_];               // ctx fp16 (hi only)
// Attention operands, pure fp16:
__device__ unsigned short g_Qf[B_ * H_ * S_ * DH_];      // [b,h,s,d] fp16
__device__ unsigned short g_Kf[B_ * H_ * S_ * DH_];      // [b,h,s,d] fp16
__device__ unsigned short g_Vf[B_ * H_ * DH_ * S_];      // [b,h,d,s] fp16

__device__ __forceinline__ float ex2f(float x) {
    float y;
    asm("ex2.approx.f32 %0, %1;" : "=f"(y) : "f"(x));
    return y;
}

__device__ __forceinline__ uint32_t smem_u32(const void* p) {
    uint32_t a;
    asm("{ .reg .u64 t; cvta.to.shared.u64 t, %1; cvt.u32.u64 %0, t; }" : "=r"(a) : "l"(p));
    return a;
}

__device__ __forceinline__ void cp16(uint32_t dst, const void* src) {
    asm volatile("cp.async.cg.shared.global [%0], [%1], 16;" :: "r"(dst), "l"(src) : "memory");
}
#define CP_COMMIT() asm volatile("cp.async.commit_group;" ::: "memory")
template <int N>
__device__ __forceinline__ void cp_wait() {
    asm volatile("cp.async.wait_group %0;" :: "n"(N) : "memory");
}

__device__ __forceinline__ void ldmatrix4(uint32_t* r, uint32_t addr) {
    asm volatile("ldmatrix.sync.aligned.m8n8.x4.shared.b16 {%0,%1,%2,%3}, [%4];"
                 : "=r"(r[0]), "=r"(r[1]), "=r"(r[2]), "=r"(r[3]) : "r"(addr));
}

__device__ __forceinline__ void mma_f16(float* d, const uint32_t* a,
                                        uint32_t b0, uint32_t b1) {
    asm volatile(
        "mma.sync.aligned.m16n8k16.row.col.f32.f16.f16.f32 "
        "{%0,%1,%2,%3}, {%4,%5,%6,%7}, {%8,%9}, {%0,%1,%2,%3};"
        : "+f"(d[0]), "+f"(d[1]), "+f"(d[2]), "+f"(d[3])
        : "r"(a[0]), "r"(a[1]), "r"(a[2]), "r"(a[3]), "r"(b0), "r"(b1));
}

// fp32 -> fp16 hi/lo bits (scalar)
__device__ __forceinline__ void hsplit(float f, unsigned short& hi, unsigned short& lo) {
    __half h = __float2half_rn(f);
    float hf = __half2float(h);
    __half l = __float2half_rn(f - hf);
    hi = __half_as_ushort(h);
    lo = __half_as_ushort(l);
}

// ============================================================================
// Pack pass: fp32 row-major -> compact fp16 hi stream (+ optional lo stream)
// ============================================================================
struct PackArgs {
    const float*    src[4];
    unsigned short* dh[4];
    unsigned short* dl[4];     // null -> skip lo
    int n;
};

__global__ __launch_bounds__(256) void pack_h16(PackArgs pa)
{
    const float* src = pa.src[blockIdx.y];
    unsigned short* dh = pa.dh[blockIdx.y];
    unsigned short* dl = pa.dl[blockIdx.y];
    int e = (blockIdx.x * 256 + threadIdx.x) * 8;
    if (e >= pa.n) return;

    float4 v0 = *(const float4*)(src + e);
    float4 v1 = *(const float4*)(src + e + 4);
    unsigned short hb[8], lb[8];
    hsplit(v0.x, hb[0], lb[0]); hsplit(v0.y, hb[1], lb[1]);
    hsplit(v0.z, hb[2], lb[2]); hsplit(v0.w, hb[3], lb[3]);
    hsplit(v1.x, hb[4], lb[4]); hsplit(v1.y, hb[5], lb[5]);
    hsplit(v1.z, hb[6], lb[6]); hsplit(v1.w, hb[7], lb[7]);
    *(uint4*)(dh + e) = *(uint4*)hb;
    if (dl) *(uint4*)(dl + e) = *(uint4*)lb;
}

// ============================================================================
// Split-fp16 projection GEMM, 128x128 tile, 256 threads (8 warps, 32x64
// warp tiles), 2-stage x 48KB -> 2 CTAs/SM for cross-CTA latency hiding.
//   C = A @ W^T;  nterm: 1 = Ah*Wh;  2 = Ah*Wh + Ah*Wl (A fp16-rounded).
//   Stage layout: [Ah 16KB][Wh 16KB][Wl 16KB]; chunk = 64 k, 8 chunks.
//   mode 0: fp16 [b,h,s,d] (Q/K)   mode 2: fp32 [M,512]   mode 3: fp16 [b,h,d,s] (V)
// ============================================================================
struct ProjArgs {
    const unsigned short* Ah[3];
    const unsigned short* Wh[3];
    const unsigned short* Wl[3];
    const float* bias[3];
    void* out[3];
    float scale[3];
    int mode[3];
    int nterm[3];
};

#define PJ_STAGE_B 49152
#define PJ_SMEM_B  (2 * PJ_STAGE_B)   // 98304 -> 2 CTAs/SM

__global__ __launch_bounds__(256, 2) void proj_mma(ProjArgs pa)
{
    const int z = blockIdx.z;
    const unsigned short* Ahp = pa.Ah[z];
    const unsigned short* Whp = pa.Wh[z];
    const unsigned short* Wlp = pa.Wl[z];
    const float* bias = pa.bias[z];
    void* outv = pa.out[z];
    const float scale = pa.scale[z];
    const int mode = pa.mode[z];
    const int nterm = pa.nterm[z];

    extern __shared__ __align__(16) char smem[];
    const uint32_t sbase = smem_u32(smem);

    const int tid = threadIdx.x;
    const int lane = tid & 31;
    const int warp = tid >> 5;         // 0..7
    const int wm = warp & 3;           // 0..3  (32-row band)
    const int wn = warp >> 2;          // 0..1  (64-col band)
    const int m0 = blockIdx.y * 128;
    const int n0 = blockIdx.x * 128;

    // loader: 256 threads, rows 0..127, each thread does 4 segs per stream
    const int lrow = tid >> 1;         // 0..127
    const int ls0  = (tid & 1) * 4;    // seg base (4 segs of 8 per 128B row)

    auto loadc = [&](int c, int st) {
        const unsigned short* As = Ahp + (size_t)(m0 + lrow) * 512 + c * 64;
        const unsigned short* Ws = Whp + (size_t)(n0 + lrow) * 512 + c * 64;
        const unsigned short* Wl = Wlp + (size_t)(n0 + lrow) * 512 + c * 64;
        const uint32_t base = sbase + st * PJ_STAGE_B + lrow * 128;
        const int rx = lrow & 7;
#pragma unroll
        for (int j = 0; j < 4; ++j) {
            int seg = ls0 + j;
            uint32_t off = 16u * (uint32_t)(seg ^ rx);
            cp16(base + off,         As + seg * 8);
            cp16(base + 16384 + off, Ws + seg * 8);
            if (nterm >= 2) cp16(base + 32768 + off, Wl + seg * 8);
        }
        CP_COMMIT();
    };

    float d[2][8][4] = {};
    const int r8 = (lane & 7) + ((lane >> 3) & 1) * 8;   // 0..15 row-in-tile
    const int sh = lane >> 4;                            // 0/1 seg offset

    // ---- prologue: 2 chunks in flight ----
    loadc(0, 0);
    loadc(1, 1);

    for (int i = 0; i < 8; ++i) {
        if (i < 7) cp_wait<1>(); else cp_wait<0>();
        __syncthreads();

        // compute on stage i&1 (chunk = 64 k = 4 k16 groups)
        {
            const uint32_t aB  = sbase + (i & 1) * PJ_STAGE_B;
            const uint32_t bB  = aB + 16384;
            const uint32_t blB = aB + 32768;
#pragma unroll
            for (int ks = 0; ks < 4; ++ks) {
                const int seg = 2 * ks + sh;
                uint32_t ah[2][4];
#pragma unroll
                for (int mt = 0; mt < 2; ++mt) {
                    int row = wm * 32 + mt * 16 + r8;
                    ldmatrix4(ah[mt], aB + row * 128 + 16 * (seg ^ (row & 7)));
                }
#pragma unroll
                for (int g = 0; g < 4; ++g) {
                    int nrow = wn * 64 + g * 16 + r8;
                    int rxn = nrow & 7;
                    uint32_t bh[4], bl[4];
                    ldmatrix4(bh, bB + nrow * 128 + 16 * (seg ^ rxn));
                    if (nterm >= 2)
                        ldmatrix4(bl, blB + nrow * 128 + 16 * (seg ^ rxn));
#pragma unroll
                    for (int q = 0; q < 2; ++q) {
                        const int nt = 2 * g + q;
#pragma unroll
                        for (int mt = 0; mt < 2; ++mt) {
                            mma_f16(d[mt][nt], ah[mt], bh[q], bh[q + 2]);        // hi*hi
                            if (nterm >= 2)
                                mma_f16(d[mt][nt], ah[mt], bl[q], bl[q + 2]);    // hi*lo
                        }
                    }
                }
            }
        }

        __syncthreads();   // 2-stage: next load overwrites the stage just read

        if (i + 2 < 8) loadc(i + 2, i & 1);
    }

    // ---- epilogue (C frag: lane row = lane/4 (+8), col = (lane%4)*2 (+1)) ----
    const int rql = lane >> 2;
    const int cql = (lane & 3) * 2;
#pragma unroll
    for (int mt = 0; mt < 2; ++mt) {
        int mbase = m0 + wm * 32 + mt * 16 + rql;
#pragma unroll
        for (int nt = 0; nt < 8; ++nt) {
            int n = n0 + wn * 64 + nt * 8 + cql;
            float2 bv = *(const float2*)&bias[n];
#pragma unroll
            for (int rr = 0; rr < 2; ++rr) {
                int m = mbase + rr * 8;
                float v0 = (d[mt][nt][rr * 2 + 0] + bv.x) * scale;
                float v1 = (d[mt][nt][rr * 2 + 1] + bv.y) * scale;
                int b = m >> 11, s = m & 2047;
                int h = n >> 6, dd = n & 63;
                if (mode == 0) {
                    // Q/K fp16 [b,h,s,d]
                    unsigned short* o16 = (unsigned short*)outv;
                    __half2 hv = __floats2half2_rn(v0, v1);
                    *(uint32_t*)&o16[(((size_t)(b * H_ + h)) * S_ + s) * 64 + dd] =
                        *reinterpret_cast<uint32_t*>(&hv);
                } else if (mode == 3) {
                    // V fp16 [b,h,d,s]
                    unsigned short* o16 = (unsigned short*)outv;
                    size_t rb = (((size_t)(b * H_ + h)) * DH_ + dd) * S_ + s;
                    o16[rb]      = __half_as_ushort(__float2half_rn(v0));
                    o16[rb + S_] = __half_as_ushort(__float2half_rn(v1));
                } else {
                    float2 v = make_float2(v0, v1);
                    *(float2*)&((float*)outv)[(size_t)m * 512 + n] = v;
                }
            }
        }
    }
}

// ============================================================================
// Tensor-core flash attention, fp16 S-phase + Ph*Vh PV phase. (validated R12)
//   CTA: 128q x 64k per tile, 8 warps x 16q.
//   Q,K fp16 [b,h,s,64] rows (128B). V fp16 [b,h,d,2048] rows.
//   Q pre-scaled by (1/sqrt(DH))*log2(e) -> exp == ex2.
//   Epilogue writes fp16 ctx (hi only).
// ============================================================================
#define AT_SQ   0
#define AT_SK   16384
#define AT_SV   (16384 + 2 * 8192)
#define AT_SMEM (16384 + 4 * 8192)     // 49152

__global__ __launch_bounds__(256) void attn_mma(
    const unsigned short* __restrict__ Qf, const unsigned short* __restrict__ Kf,
    const unsigned short* __restrict__ Vf, const int* __restrict__ lens,
    unsigned short* __restrict__ ctxh)
{
    extern __shared__ __align__(16) char smem[];
    const uint32_t sb = smem_u32(smem);

    const int tid = threadIdx.x;
    const int lane = tid & 31;
    const int warp = tid >> 5;
    const int q0 = blockIdx.x * 128;
    const int h = blockIdx.y;
    const int b = blockIdx.z;
    const int len = lens[b];

    const size_t bh = (size_t)(b * H_ + h);
    const unsigned short* Qg = Qf + (bh * S_ + q0) * 64;
    const unsigned short* Kg = Kf + bh * S_ * 64;
    const unsigned short* Vg = Vf + bh * (size_t)DH_ * S_;

    const int r8 = (lane & 7) + ((lane >> 3) & 1) * 8;   // 0..15
    const int sh = lane >> 4;                            // 0/1
    const int u2 = (lane & 3) * 2;                       // col pair base
    const int rx = r8 & 7;

    // ---- load Q tile (128 rows x 128B), one commit group ----
#pragma unroll
    for (int j = 0; j < 4; ++j) {
        int idx = j * 256 + tid;
        int row = idx >> 3, seg = idx & 7;
        cp16(sb + AT_SQ + row * 128 + 16 * (seg ^ (row & 7)), Qg + (size_t)row * 64 + seg * 8);
    }
    CP_COMMIT();

    // ---- K/V tile loader (4 cp16/thread, one group) ----
    auto loadKV = [&](int kt0, int buf) {
        const uint32_t dk = sb + AT_SK + buf * 8192;
        const uint32_t dv = sb + AT_SV + buf * 8192;
#pragma unroll
        for (int j = 0; j < 2; ++j) {
            int idx = j * 256 + tid;
            int row = idx >> 3, seg = idx & 7;
            uint32_t off = row * 128 + 16 * (seg ^ (row & 7));
            cp16(dk + off, Kg + ((size_t)(kt0 + row)) * 64 + seg * 8);
            cp16(dv + off, Vg + (size_t)row * S_ + kt0 + seg * 8);
        }
        CP_COMMIT();
    };

    loadKV(0, 0);
    cp_wait<0>();
    __syncthreads();

    // ---- extract Q A-frags (register resident): qa[kg] ----
    uint32_t qa[4][4];
    {
        const int qrow = 16 * warp + r8;
        const uint32_t qb = sb + AT_SQ + qrow * 128;
#pragma unroll
        for (int kg = 0; kg < 4; ++kg)
            ldmatrix4(qa[kg], qb + 16 * ((2 * kg + sh) ^ rx));
    }

    float oacc[8][4] = {};
    float m0 = -1e30f, m1 = -1e30f, l0 = 0.f, l1 = 0.f;

    const int nkt = (len + 63) >> 6;

    for (int t = 0; t < nkt; ++t) {
        if (t + 1 < nkt) loadKV((t + 1) * 64, (t + 1) & 1);

        const uint32_t kb = sb + AT_SK + (t & 1) * 8192;
        const uint32_t vbuf = sb + AT_SV + (t & 1) * 8192;

        // ---- S = Q K^T (pure fp16) ----
        float sacc[8][4] = {};
#pragma unroll
        for (int kg = 0; kg < 4; ++kg) {
            const uint32_t off = 16u * (uint32_t)((2 * kg + sh) ^ rx);
#pragma unroll
            for (int g = 0; g < 4; ++g) {
                uint32_t kh[4];
                ldmatrix4(kh, kb + (16 * g + r8) * 128 + off);
#pragma unroll
                for (int q = 0; q < 2; ++q)
                    mma_f16(sacc[2 * g + q], qa[kg], kh[q], kh[q + 2]);
            }
        }

        // ---- mask tail keys ----
        const int kt0 = t * 64;
        if (kt0 + 64 > len) {
#pragma unroll
            for (int nt = 0; nt < 8; ++nt) {
                int c0 = kt0 + nt * 8 + u2;
                if (c0 >= len)     { sacc[nt][0] = -1e30f; sacc[nt][2] = -1e30f; }
                if (c0 + 1 >= len) { sacc[nt][1] = -1e30f; sacc[nt][3] = -1e30f; }
            }
        }

        // ---- online softmax (rows l/4 and l/4+8; quad shfl reductions) ----
        float mx0 = -1e30f, mx1 = -1e30f;
#pragma unroll
        for (int nt = 0; nt < 8; ++nt) {
            mx0 = fmaxf(mx0, fmaxf(sacc[nt][0], sacc[nt][1]));
            mx1 = fmaxf(mx1, fmaxf(sacc[nt][2], sacc[nt][3]));
        }
        mx0 = fmaxf(mx0, __shfl_xor_sync(0xffffffffu, mx0, 1));
        mx0 = fmaxf(mx0, __shfl_xor_sync(0xffffffffu, mx0, 2));
        mx1 = fmaxf(mx1, __shfl_xor_sync(0xffffffffu, mx1, 1));
        mx1 = fmaxf(mx1, __shfl_xor_sync(0xffffffffu, mx1, 2));

        const float mn0 = fmaxf(m0, mx0), mn1 = fmaxf(m1, mx1);
        const float e0 = ex2f(m0 - mn0), e1 = ex2f(m1 - mn1);
        m0 = mn0; m1 = mn1;

        float s0 = 0.f, s1 = 0.f;
#pragma unroll
        for (int nt = 0; nt < 8; ++nt) {
            float p;
            p = ex2f(sacc[nt][0] - mn0); sacc[nt][0] = p; s0 += p;
            p = ex2f(sacc[nt][1] - mn0); sacc[nt][1] = p; s0 += p;
            p = ex2f(sacc[nt][2] - mn1); sacc[nt][2] = p; s1 += p;
            p = ex2f(sacc[nt][3] - mn1); sacc[nt][3] = p; s1 += p;
        }
        s0 += __shfl_xor_sync(0xffffffffu, s0, 1);
        s0 += __shfl_xor_sync(0xffffffffu, s0, 2);
        s1 += __shfl_xor_sync(0xffffffffu, s1, 1);
        s1 += __shfl_xor_sync(0xffffffffu, s1, 2);
        l0 = l0 * e0 + s0;
        l1 = l1 * e1 + s1;

#pragma unroll
        for (int nt = 0; nt < 8; ++nt) {
            oacc[nt][0] *= e0; oacc[nt][1] *= e0;
            oacc[nt][2] *= e1; oacc[nt][3] *= e1;
        }

        // ---- O += Ph Vh (P fp16-rounded; softmax-bounded error) ----
#pragma unroll
        for (int u = 0; u < 4; ++u) {          // k16 subgroup
            const int g0 = 2 * u;
            uint32_t ph[4];
            __half2 t0 = __floats2half2_rn(sacc[g0][0], sacc[g0][1]);
            __half2 t1 = __floats2half2_rn(sacc[g0][2], sacc[g0][3]);
            __half2 t2 = __floats2half2_rn(sacc[g0 + 1][0], sacc[g0 + 1][1]);
            __half2 t3 = __floats2half2_rn(sacc[g0 + 1][2], sacc[g0 + 1][3]);
            ph[0] = *reinterpret_cast<uint32_t*>(&t0);
            ph[1] = *reinterpret_cast<uint32_t*>(&t1);
            ph[2] = *reinterpret_cast<uint32_t*>(&t2);
            ph[3] = *reinterpret_cast<uint32_t*>(&t3);

            const uint32_t off = 16u * (uint32_t)((2 * u + sh) ^ rx);
#pragma unroll
            for (int dt = 0; dt < 4; ++dt) {
                uint32_t vh[4];
                ldmatrix4(vh, vbuf + (16 * dt + r8) * 128 + off);
#pragma unroll
                for (int q = 0; q < 2; ++q)
                    mma_f16(oacc[2 * dt + q], ph, vh[q], vh[q + 2]);
            }
        }

        if (t + 1 < nkt) cp_wait<0>();
        __syncthreads();
    }

    // ---- write fp16 ctx (hi only) [b*S+q, 512] ----
    const float inv0 = 1.0f / l0;
    const float inv1 = 1.0f / l1;
    const int qg0 = q0 + 16 * warp + (lane >> 2);
    const int qg1 = qg0 + 8;
    const size_t rb0 = ((size_t)b * S_ + qg0) * 512;
    const size_t rb1 = ((size_t)b * S_ + qg1) * 512;
#pragma unroll
    for (int nt = 0; nt < 8; ++nt) {
        int n = h * 64 + nt * 8 + u2;
        __half2 hv0 = __floats2half2_rn(oacc[nt][0] * inv0, oacc[nt][1] * inv0);
        __half2 hv1 = __floats2half2_rn(oacc[nt][2] * inv1, oacc[nt][3] * inv1);
        *(uint32_t*)&ctxh[rb0 + n] = *reinterpret_cast<uint32_t*>(&hv0);
        *(uint32_t*)&ctxh[rb1 + n] = *reinterpret_cast<uint32_t*>(&hv1);
    }
}

// ---------------------------------------------------------------------------

extern "C" void kernel_launch(void* const* d_in, const int* in_sizes, int n_in,
                              void* d_out, int out_size)
{
    const float* x_Q = (const float*)d_in[0];
    const float* x_K = (const float*)d_in[1];
    const float* x_V = (const float*)d_in[2];
    const float* Wq  = (const float*)d_in[3];
    const float* bq  = (const float*)d_in[4];
    const float* Wk  = (const float*)d_in[5];
    const float* bk  = (const float*)d_in[6];
    const float* Wv  = (const float*)d_in[7];
    const float* bv  = (const float*)d_in[8];
    const float* Wo  = (const float*)d_in[9];
    const float* bo  = (const float*)d_in[10];
    const int*   lens = (const int*)d_in[11];
    float* out = (float*)d_out;

    unsigned short *xQh, *xKh, *xVh, *Wqh, *Wkh, *Wvh, *Wvl, *Woh, *Wol;
    unsigned short *ctxh, *Qf, *Kf, *Vf;
    cudaGetSymbolAddress((void**)&xQh, g_xQh);
    cudaGetSymbolAddress((void**)&xKh, g_xKh);
    cudaGetSymbolAddress((void**)&xVh, g_xVh);
    cudaGetSymbolAddress((void**)&Wqh, g_Wqh);
    cudaGetSymbolAddress((void**)&Wkh, g_Wkh);
    cudaGetSymbolAddress((void**)&Wvh, g_Wvh);
    cudaGetSymbolAddress((void**)&Wvl, g_Wvl);
    cudaGetSymbolAddress((void**)&Woh, g_Woh);
    cudaGetSymbolAddress((void**)&Wol, g_Wol);
    cudaGetSymbolAddress((void**)&ctxh, g_ctxh);
    cudaGetSymbolAddress((void**)&Qf,  g_Qf);
    cudaGetSymbolAddress((void**)&Kf,  g_Kf);
    cudaGetSymbolAddress((void**)&Vf,  g_Vf);

    cudaFuncSetAttribute(proj_mma, cudaFuncAttributeMaxDynamicSharedMemorySize, PJ_SMEM_B);
    cudaFuncSetAttribute(attn_mma, cudaFuncAttributeMaxDynamicSharedMemorySize, AT_SMEM);

    // ---- pack passes (2 launches) ----
    {
        PackArgs px;
        px.src[0] = x_Q; px.dh[0] = xQh; px.dl[0] = nullptr;
        px.src[1] = x_K; px.dh[1] = xKh; px.dl[1] = nullptr;
        px.src[2] = x_V; px.dh[2] = xVh; px.dl[2] = nullptr;
        px.src[3] = x_Q; px.dh[3] = xQh; px.dl[3] = nullptr;   // unused lane
        px.n = M_ * D_;
        dim3 gx((M_ * D_ / 8 + 255) / 256, 3);
        pack_h16<<<gx, 256>>>(px);

        PackArgs pw;
        pw.src[0] = Wq; pw.dh[0] = Wqh; pw.dl[0] = nullptr;
        pw.src[1] = Wk; pw.dh[1] = Wkh; pw.dl[1] = nullptr;
        pw.src[2] = Wv; pw.dh[2] = Wvh; pw.dl[2] = Wvl;
        pw.src[3] = Wo; pw.dh[3] = Woh; pw.dl[3] = Wol;
        pw.n = D_ * D_;
        dim3 gw((D_ * D_ / 8 + 255) / 256, 4);
        pack_h16<<<gw, 256>>>(pw);
    }

    // scale = 1/sqrt(DH) * log2(e), folded into Q projection (incl. bias)
    const float qscale = 0.125f * 1.4426950408889634f;

    // ---- batched Q/K/V projections (one launch, 48KB stage x2 -> 2 CTA/SM) ----
    {
        ProjArgs pa;
        pa.Ah[0] = xQh; pa.Wh[0] = Wqh; pa.Wl[0] = nullptr;
        pa.bias[0] = bq; pa.out[0] = Qf; pa.scale[0] = qscale; pa.mode[0] = 0; pa.nterm[0] = 1;
        pa.Ah[1] = xKh; pa.Wh[1] = Wkh; pa.Wl[1] = nullptr;
        pa.bias[1] = bk; pa.out[1] = Kf; pa.scale[1] = 1.0f;   pa.mode[1] = 0; pa.nterm[1] = 1;
        pa.Ah[2] = xVh; pa.Wh[2] = Wvh; pa.Wl[2] = Wvl;
        pa.bias[2] = bv; pa.out[2] = Vf; pa.scale[2] = 1.0f;   pa.mode[2] = 3; pa.nterm[2] = 2;
        dim3 g(D_ / 128, M_ / 128, 3);
        proj_mma<<<g, 256, PJ_SMEM_B>>>(pa);
    }

    dim3 gattn(S_ / 128, H_, B_);
    attn_mma<<<gattn, 256, AT_SMEM>>>(Qf, Kf, Vf, lens, ctxh);

    // ---- final projection (2-term: ctx fp16-rounded, W exact) ----
    {
        ProjArgs pa;
        pa.Ah[0] = ctxh; pa.Wh[0] = Woh; pa.Wl[0] = Wol;
        pa.bias[0] = bo; pa.out[0] = out; pa.scale[0] = 1.0f; pa.mode[0] = 2; pa.nterm[0] = 2;
        pa.Ah[1] = ctxh; pa.Wh[1] = Woh; pa.Wl[1] = Wol;
        pa.bias[1] = bo; pa.out[1] = out; pa.scale[1] = 1.0f; pa.mode[1] = 2; pa.nterm[1] = 2;
        pa.Ah[2] = ctxh; pa.Wh[2] = Woh; pa.Wl[2] = Wol;
        pa.bias[2] = bo; pa.out[2] = out; pa.scale[2] = 1.0f; pa.mode[2] = 2; pa.nterm[2] = 2;
        dim3 g(D_ / 128, M_ / 128, 1);
        proj_mma<<<g, 256, PJ_SMEM_B>>>(pa);
    }
}